// round 9
// baseline (speedup 1.0000x reference)
#include <cuda_runtime.h>
#include <math.h>

#define T_TOK 2048
#define HIDDEN 2048
#define NH 32
#define NKV 8
#define HD 128
#define QSIZE (NH*HD)              // 4096
#define KVSIZE (NKV*HD)            // 1024
#define QKVN (QSIZE + 2*KVSIZE)    // 6144
#define WINDOW 512
#define TQ 32
#define SPAD 548                   // scores row pitch (floats)
#define KP 129                     // transposed-K pitch
#define VP 132                     // V row pitch

// -------- scratch (device globals: allocation-free) --------
__device__ float g_qkv[T_TOK * QKVN];     // 50.3 MB
__device__ float g_gate[T_TOK * NH];      // 0.26 MB
__device__ float g_attn[T_TOK * QSIZE];   // 33.5 MB

// =====================================================================
// SGEMM: C[M,N] = A[M,K] @ B[K,N], row-major, 128x128 tile, BK=8,
// 256 threads, 8x8 per-thread microtile.
// =====================================================================
__global__ __launch_bounds__(256) void sgemm128(
    const float* __restrict__ A, const float* __restrict__ B,
    float* __restrict__ C, int M, int N, int K)
{
    __shared__ float As[8][128];   // As[k][m]
    __shared__ float Bs[8][128];   // Bs[k][n]

    const int m0 = blockIdx.y * 128;
    const int n0 = blockIdx.x * 128;
    const int t  = threadIdx.x;
    const int tx = t & 15;
    const int ty = t >> 4;

    float acc[8][8];
#pragma unroll
    for (int i = 0; i < 8; i++)
#pragma unroll
        for (int j = 0; j < 8; j++) acc[i][j] = 0.f;

    const int arow = t >> 1;
    const int ak   = (t & 1) * 4;
    const int brow = t >> 5;
    const int bn   = (t & 31) * 4;

    const float* Ap = A + (size_t)(m0 + arow) * K + ak;
    const float* Bp = B + (size_t)brow * N + n0 + bn;

    for (int k0 = 0; k0 < K; k0 += 8) {
        float4 av = *(const float4*)(Ap + k0);
        float4 bv = *(const float4*)(Bp + (size_t)k0 * N);
        __syncthreads();
        As[ak + 0][arow] = av.x;
        As[ak + 1][arow] = av.y;
        As[ak + 2][arow] = av.z;
        As[ak + 3][arow] = av.w;
        *(float4*)&Bs[brow][bn] = bv;
        __syncthreads();
#pragma unroll
        for (int kk = 0; kk < 8; kk++) {
            float4 a0 = *(float4*)&As[kk][ty * 8];
            float4 a1 = *(float4*)&As[kk][ty * 8 + 4];
            float4 b0 = *(float4*)&Bs[kk][tx * 8];
            float4 b1 = *(float4*)&Bs[kk][tx * 8 + 4];
            float ar[8] = {a0.x, a0.y, a0.z, a0.w, a1.x, a1.y, a1.z, a1.w};
            float br[8] = {b0.x, b0.y, b0.z, b0.w, b1.x, b1.y, b1.z, b1.w};
#pragma unroll
            for (int i = 0; i < 8; i++)
#pragma unroll
                for (int j = 0; j < 8; j++)
                    acc[i][j] = fmaf(ar[i], br[j], acc[i][j]);
        }
    }

#pragma unroll
    for (int i = 0; i < 8; i++) {
        float* Cr = C + (size_t)(m0 + ty * 8 + i) * N + n0 + tx * 8;
        *(float4*)Cr       = make_float4(acc[i][0], acc[i][1], acc[i][2], acc[i][3]);
        *(float4*)(Cr + 4) = make_float4(acc[i][4], acc[i][5], acc[i][6], acc[i][7]);
    }
}

// =====================================================================
// RMSNorm + RoPE in place. grid (T, 40): y<32 -> q head, else k head.
// NOTE: sincosf(x, &s, &c) -- sin pointer FIRST (that was the bug).
// =====================================================================
__global__ __launch_bounds__(128) void norm_rope_k(
    const int* __restrict__ pos,
    const float* __restrict__ qw, const float* __restrict__ kw)
{
    const int t  = blockIdx.x;
    const int hh = blockIdx.y;
    const bool is_q = (hh < NH);
    float* x = g_qkv + (size_t)t * QKVN +
               (is_q ? hh * HD : QSIZE + (hh - NH) * HD);
    const float* w = is_q ? qw : kw;
    const int d = threadIdx.x;

    float v = x[d];
    float ss = v * v;
#pragma unroll
    for (int o = 16; o; o >>= 1) ss += __shfl_xor_sync(0xffffffffu, ss, o);
    __shared__ float red[4];
    if ((d & 31) == 0) red[d >> 5] = ss;
    __syncthreads();
    float r = rsqrtf((red[0] + red[1] + red[2] + red[3]) * (1.0f / HD) + 1e-6f);

    __shared__ float xs[HD];
    xs[d] = v * r * w[d];
    __syncthreads();

    if (d < 64) {
        float inv = powf(10000.0f, -(float)(2 * d) * (1.0f / HD));
        float ang = (float)pos[t] * inv;
        float s, c;
        sincosf(ang, &s, &c);          // sin first, cos second
        float x1 = xs[d], x2 = xs[d + 64];
        x[d]      = x1 * c - x2 * s;
        x[d + 64] = x2 * c + x1 * s;
    }
}

// =====================================================================
// Gate: g[t,h] = softplus(X[t,:] @ Wg[:,h]). grid T, block 256.
// =====================================================================
__global__ __launch_bounds__(256) void gate_k(
    const float* __restrict__ X, const float* __restrict__ wg)
{
    const int t   = blockIdx.x;
    const int h   = threadIdx.x >> 3;   // 0..31
    const int sub = threadIdx.x & 7;    // 0..7
    const float* xr = X + (size_t)t * HIDDEN;

    float acc = 0.f;
    for (int k = sub; k < HIDDEN; k += 8)
        acc = fmaf(xr[k], wg[(size_t)k * NH + h], acc);
    acc += __shfl_xor_sync(0xffffffffu, acc, 1);
    acc += __shfl_xor_sync(0xffffffffu, acc, 2);
    acc += __shfl_xor_sync(0xffffffffu, acc, 4);
    if (sub == 0) {
        float sp = (acc > 20.f) ? acc : log1pf(expf(acc));
        g_gate[(size_t)t * NH + h] = sp;
    }
}

// =====================================================================
// Sliding-window attention. grid (T/32, 32 heads), block 256.
// Scores in SMEM (value-masked), full-row softmax, PV, gate epilogue.
// =====================================================================
#define ATTN_SMEM_FLOATS (TQ*132 + 128*VP + TQ*SPAD)
#define ATTN_SMEM_BYTES  (ATTN_SMEM_FLOATS * 4)

__global__ __launch_bounds__(256) void attn_k()
{
    extern __shared__ float sm[];
    float* qs  = sm;                 // [TQ][132]
    float* kvt = sm + TQ * 132;      // K^T [128][KP] or V [128][VP]
    float* sc  = kvt + 128 * VP;     // [TQ][SPAD]

    const int t0  = blockIdx.x * TQ;
    const int h   = blockIdx.y;
    const int kvh = h >> 2;          // head h -> kv head h/4
    const int tid = threadIdx.x;
    const int wg  = tid >> 5;
    const int ln  = tid & 31;

    const int s_min  = max(0, t0 - (WINDOW - 1));
    const int s_end  = t0 + TQ;
    const int srange = s_end - s_min;          // <= 543
    const float scale = 0.08838834764831845f;  // 128^-0.5

    // ---- load Q tile (pre-scaled) ----
    for (int i = tid; i < TQ * 32; i += 256) {
        int m = i >> 5, c = (i & 31) * 4;
        float4 v = *(const float4*)(g_qkv + (size_t)(t0 + m) * QKVN + h * HD + c);
        v.x *= scale; v.y *= scale; v.z *= scale; v.w *= scale;
        *(float4*)(qs + m * 132 + c) = v;
    }

    // ---- QK^T in chunks of 128 keys ----
    for (int cs = s_min; cs < s_end; cs += 128) {
        const int cn = min(128, s_end - cs);
        __syncthreads();
        for (int i = tid; i < cn * 32; i += 256) {
            int j = i >> 5, c = (i & 31) * 4;
            float4 v = *(const float4*)(g_qkv + (size_t)(cs + j) * QKVN +
                                        QSIZE + kvh * HD + c);
            kvt[(c + 0) * KP + j] = v.x;
            kvt[(c + 1) * KP + j] = v.y;
            kvt[(c + 2) * KP + j] = v.z;
            kvt[(c + 3) * KP + j] = v.w;
        }
        __syncthreads();

        float acc[4][4];
#pragma unroll
        for (int i = 0; i < 4; i++)
#pragma unroll
            for (int j = 0; j < 4; j++) acc[i][j] = 0.f;

#pragma unroll 4
        for (int k = 0; k < HD; k++) {
            float a[4], b[4];
#pragma unroll
            for (int i = 0; i < 4; i++) a[i] = qs[(wg + 8 * i) * 132 + k];
#pragma unroll
            for (int j = 0; j < 4; j++) b[j] = kvt[k * KP + ln + 32 * j];
#pragma unroll
            for (int i = 0; i < 4; i++)
#pragma unroll
                for (int j = 0; j < 4; j++)
                    acc[i][j] = fmaf(a[i], b[j], acc[i][j]);
        }

        const int off = cs - s_min;
#pragma unroll
        for (int j = 0; j < 4; j++) {
            int n = ln + 32 * j;
            if (n < cn) {
                int s_abs = cs + n;
#pragma unroll
                for (int i = 0; i < 4; i++) {
                    int diff = (t0 + wg + 8 * i) - s_abs;
                    float val = (diff >= 0 && diff < WINDOW) ? acc[i][j] : -1e30f;
                    sc[(wg + 8 * i) * SPAD + off + n] = val;
                }
            }
        }
    }
    __syncthreads();

    // ---- softmax over full row [0, srange) ----
    for (int r = wg; r < TQ; r += 8) {
        float* row = sc + r * SPAD;
        float mx = -1e30f;
        for (int i = ln; i < srange; i += 32) mx = fmaxf(mx, row[i]);
#pragma unroll
        for (int o = 16; o; o >>= 1) mx = fmaxf(mx, __shfl_xor_sync(0xffffffffu, mx, o));
        float sum = 0.f;
        for (int i = ln; i < srange; i += 32) {
            float e = expf(row[i] - mx);
            row[i] = e;
            sum += e;
        }
#pragma unroll
        for (int o = 16; o; o >>= 1) sum += __shfl_xor_sync(0xffffffffu, sum, o);
        float inv = 1.f / sum;
        for (int i = ln; i < srange; i += 32) row[i] *= inv;
    }
    __syncthreads();

    // ---- PV ----
    float4 o[4];
#pragma unroll
    for (int i = 0; i < 4; i++) o[i] = make_float4(0.f, 0.f, 0.f, 0.f);

    for (int cs = s_min; cs < s_end; cs += 128) {
        const int cn = min(128, s_end - cs);
        __syncthreads();
        for (int i = tid; i < cn * 32; i += 256) {
            int j = i >> 5, c = (i & 31) * 4;
            float4 v = *(const float4*)(g_qkv + (size_t)(cs + j) * QKVN +
                                        QSIZE + KVSIZE + kvh * HD + c);
            *(float4*)(kvt + j * VP + c) = v;
        }
        __syncthreads();
        const int off = cs - s_min;
        for (int j = 0; j < cn; j++) {
            float4 v = *(float4*)(kvt + j * VP + ln * 4);
#pragma unroll
            for (int i = 0; i < 4; i++) {
                float p = sc[(wg + 8 * i) * SPAD + off + j];
                o[i].x = fmaf(p, v.x, o[i].x);
                o[i].y = fmaf(p, v.y, o[i].y);
                o[i].z = fmaf(p, v.z, o[i].z);
                o[i].w = fmaf(p, v.w, o[i].w);
            }
        }
    }

    // ---- epilogue: gate, store ----
#pragma unroll
    for (int i = 0; i < 4; i++) {
        int m = wg + 8 * i;
        float g = g_gate[(size_t)(t0 + m) * NH + h];
        float4 r = o[i];
        r.x *= g; r.y *= g; r.z *= g; r.w *= g;
        *(float4*)(g_attn + (size_t)(t0 + m) * QSIZE + h * HD + ln * 4) = r;
    }
}

// =====================================================================
// launch
// =====================================================================
extern "C" void kernel_launch(void* const* d_in, const int* in_sizes, int n_in,
                              void* d_out, int out_size)
{
    const int*   positions = 0;
    const float* X    = 0;
    const float* Wqkv = 0;
    const float* Wo   = 0;
    const float* Wg   = 0;
    const float* qw   = 0;
    const float* kw   = 0;

    for (int i = 0; i < n_in; i++) {
        switch (in_sizes[i]) {
            case T_TOK:          positions = (const int*)d_in[i];     break;
            case T_TOK*HIDDEN:   X    = (const float*)d_in[i];        break;
            case HIDDEN*QKVN:    Wqkv = (const float*)d_in[i];        break;
            case QSIZE*HIDDEN:   Wo   = (const float*)d_in[i];        break;
            case HIDDEN*NH:      Wg   = (const float*)d_in[i];        break;
            case HD:             if (!qw) qw = (const float*)d_in[i];
                                 else     kw = (const float*)d_in[i]; break;
            default: break;
        }
    }

    float *qkv_p, *attn_p;
    cudaGetSymbolAddress((void**)&qkv_p,  g_qkv);
    cudaGetSymbolAddress((void**)&attn_p, g_attn);
    float* out = (float*)d_out;

    // 1) QKV GEMM: [2048,2048] x [2048,6144]
    sgemm128<<<dim3(QKVN / 128, T_TOK / 128), 256>>>(X, Wqkv, qkv_p,
                                                     T_TOK, QKVN, HIDDEN);
    // 2) RMSNorm + RoPE in place (q and k heads)
    norm_rope_k<<<dim3(T_TOK, NH + NKV), 128>>>(positions, qw, kw);
    // 3) Gate
    gate_k<<<T_TOK, 256>>>(X, Wg);
    // 4) Attention (+ gate fused)
    cudaFuncSetAttribute(attn_k, cudaFuncAttributeMaxDynamicSharedMemorySize,
                         ATTN_SMEM_BYTES);
    attn_k<<<dim3(T_TOK / TQ, NH), 256, ATTN_SMEM_BYTES>>>();
    // 5) Output GEMM: [2048,4096] x [4096,2048]
    sgemm128<<<dim3(HIDDEN / 128, T_TOK / 128), 256>>>(attn_p, Wo, out,
                                                       T_TOK, HIDDEN, QSIZE);
    (void)out_size;
}

// round 11
// speedup vs baseline: 1.7655x; 1.7655x over previous
#include <cuda_runtime.h>
#include <math.h>
#include <stdint.h>

#define T_TOK 2048
#define HIDDEN 2048
#define NH 32
#define NKV 8
#define HD 128
#define QSIZE (NH*HD)              // 4096
#define KVSIZE (NKV*HD)            // 1024
#define QKVN (QSIZE + 2*KVSIZE)    // 6144
#define WINDOW 512
#define TQ 32
#define SPAD 548
#define KP 129
#define VP 132

// -------- scratch (device globals: allocation-free) --------
__device__ float g_qkv[T_TOK * QKVN];     // 50.3 MB
__device__ float g_gate[T_TOK * NH];      // 0.26 MB
__device__ float g_attn[T_TOK * QSIZE];   // 33.5 MB

// =====================================================================
// TF32 tensor-core GEMM: C[M,N] = A[M,K] @ B[K,N], row-major.
// 128x128 block tile, 8 warps (2x4), warp tile 64x32, k-chunk 16.
// mma.sync.aligned.m16n8k8.row.col.f32.tf32.tf32.f32
// =====================================================================
__device__ __forceinline__ float to_tf32(float x)
{
    uint32_t r;
    asm("cvt.rna.tf32.f32 %0, %1;" : "=r"(r) : "f"(x));
    return __uint_as_float(r);
}

__device__ __forceinline__ void mma_tf32(
    float* d, const uint32_t* a, const uint32_t* b)
{
    asm volatile(
        "mma.sync.aligned.m16n8k8.row.col.f32.tf32.tf32.f32 "
        "{%0,%1,%2,%3}, {%4,%5,%6,%7}, {%8,%9}, {%0,%1,%2,%3};\n"
        : "+f"(d[0]), "+f"(d[1]), "+f"(d[2]), "+f"(d[3])
        : "r"(a[0]), "r"(a[1]), "r"(a[2]), "r"(a[3]),
          "r"(b[0]), "r"(b[1]));
}

__global__ __launch_bounds__(256) void gemm_tf32(
    const float* __restrict__ A, const float* __restrict__ B,
    float* __restrict__ C, int M, int N, int K)
{
    __shared__ float As[16][136];   // As[k][m], pitch 136 -> conflict-free frags
    __shared__ float Bs[16][136];   // Bs[k][n]

    const int m0 = blockIdx.y * 128;
    const int n0 = blockIdx.x * 128;
    const int tid  = threadIdx.x;
    const int wid  = tid >> 5;
    const int lane = tid & 31;
    const int wm = (wid >> 2) * 64;      // warp m offset: 0,64
    const int wn = (wid & 3) * 32;       // warp n offset: 0..96
    const int grp = lane >> 2;           // 0..7
    const int tig = lane & 3;            // 0..3

    float acc[4][4][4];
#pragma unroll
    for (int mf = 0; mf < 4; mf++)
#pragma unroll
        for (int nf = 0; nf < 4; nf++)
#pragma unroll
            for (int r = 0; r < 4; r++) acc[mf][nf][r] = 0.f;

    const int am = tid >> 1;             // 0..127
    const int ak = (tid & 1) * 8;        // 0,8
    const int bk = tid >> 4;             // 0..15
    const int bn = (tid & 15) * 8;       // 0..120

    const float* Ap = A + (size_t)(m0 + am) * K + ak;
    const float* Bp = B + (size_t)bk * N + n0 + bn;

    for (int k0 = 0; k0 < K; k0 += 16) {
        float4 av0 = *(const float4*)(Ap + k0);
        float4 av1 = *(const float4*)(Ap + k0 + 4);
        float4 bv0 = *(const float4*)(Bp + (size_t)k0 * N);
        float4 bv1 = *(const float4*)(Bp + (size_t)k0 * N + 4);
        __syncthreads();
        As[ak + 0][am] = to_tf32(av0.x);
        As[ak + 1][am] = to_tf32(av0.y);
        As[ak + 2][am] = to_tf32(av0.z);
        As[ak + 3][am] = to_tf32(av0.w);
        As[ak + 4][am] = to_tf32(av1.x);
        As[ak + 5][am] = to_tf32(av1.y);
        As[ak + 6][am] = to_tf32(av1.z);
        As[ak + 7][am] = to_tf32(av1.w);
        Bs[bk][bn + 0] = to_tf32(bv0.x);
        Bs[bk][bn + 1] = to_tf32(bv0.y);
        Bs[bk][bn + 2] = to_tf32(bv0.z);
        Bs[bk][bn + 3] = to_tf32(bv0.w);
        Bs[bk][bn + 4] = to_tf32(bv1.x);
        Bs[bk][bn + 5] = to_tf32(bv1.y);
        Bs[bk][bn + 6] = to_tf32(bv1.z);
        Bs[bk][bn + 7] = to_tf32(bv1.w);
        __syncthreads();

#pragma unroll
        for (int ks = 0; ks < 16; ks += 8) {
            uint32_t af[4][4], bf[4][2];
#pragma unroll
            for (int mf = 0; mf < 4; mf++) {
                int row = wm + mf * 16 + grp;
                af[mf][0] = __float_as_uint(As[ks + tig    ][row]);
                af[mf][1] = __float_as_uint(As[ks + tig    ][row + 8]);
                af[mf][2] = __float_as_uint(As[ks + tig + 4][row]);
                af[mf][3] = __float_as_uint(As[ks + tig + 4][row + 8]);
            }
#pragma unroll
            for (int nf = 0; nf < 4; nf++) {
                int col = wn + nf * 8 + grp;
                bf[nf][0] = __float_as_uint(Bs[ks + tig    ][col]);
                bf[nf][1] = __float_as_uint(Bs[ks + tig + 4][col]);
            }
#pragma unroll
            for (int mf = 0; mf < 4; mf++)
#pragma unroll
                for (int nf = 0; nf < 4; nf++)
                    mma_tf32(acc[mf][nf], af[mf], bf[nf]);
        }
    }

    // epilogue
#pragma unroll
    for (int mf = 0; mf < 4; mf++) {
        int row = m0 + wm + mf * 16 + grp;
#pragma unroll
        for (int nf = 0; nf < 4; nf++) {
            int col = n0 + wn + nf * 8 + 2 * tig;
            float2 c01 = make_float2(acc[mf][nf][0], acc[mf][nf][1]);
            float2 c23 = make_float2(acc[mf][nf][2], acc[mf][nf][3]);
            *(float2*)(C + (size_t)row * N + col)       = c01;
            *(float2*)(C + (size_t)(row + 8) * N + col) = c23;
        }
    }
}

// =====================================================================
// RMSNorm + RoPE in place. grid (T, 40). sincosf(x, &s, &c): sin FIRST.
// =====================================================================
__global__ __launch_bounds__(128) void norm_rope_k(
    const int* __restrict__ pos,
    const float* __restrict__ qw, const float* __restrict__ kw)
{
    const int t  = blockIdx.x;
    const int hh = blockIdx.y;
    const bool is_q = (hh < NH);
    float* x = g_qkv + (size_t)t * QKVN +
               (is_q ? hh * HD : QSIZE + (hh - NH) * HD);
    const float* w = is_q ? qw : kw;
    const int d = threadIdx.x;

    float v = x[d];
    float ss = v * v;
#pragma unroll
    for (int o = 16; o; o >>= 1) ss += __shfl_xor_sync(0xffffffffu, ss, o);
    __shared__ float red[4];
    if ((d & 31) == 0) red[d >> 5] = ss;
    __syncthreads();
    float r = rsqrtf((red[0] + red[1] + red[2] + red[3]) * (1.0f / HD) + 1e-6f);

    __shared__ float xs[HD];
    xs[d] = v * r * w[d];
    __syncthreads();

    if (d < 64) {
        float inv = powf(10000.0f, -(float)(2 * d) * (1.0f / HD));
        float ang = (float)pos[t] * inv;
        float s, c;
        sincosf(ang, &s, &c);
        float x1 = xs[d], x2 = xs[d + 64];
        x[d]      = x1 * c - x2 * s;
        x[d + 64] = x2 * c + x1 * s;
    }
}

// =====================================================================
// Gate: softplus(X @ Wg). grid T, block 256.
// =====================================================================
__global__ __launch_bounds__(256) void gate_k(
    const float* __restrict__ X, const float* __restrict__ wg)
{
    const int t   = blockIdx.x;
    const int h   = threadIdx.x >> 3;
    const int sub = threadIdx.x & 7;
    const float* xr = X + (size_t)t * HIDDEN;

    float acc = 0.f;
    for (int k = sub; k < HIDDEN; k += 8)
        acc = fmaf(xr[k], wg[(size_t)k * NH + h], acc);
    acc += __shfl_xor_sync(0xffffffffu, acc, 1);
    acc += __shfl_xor_sync(0xffffffffu, acc, 2);
    acc += __shfl_xor_sync(0xffffffffu, acc, 4);
    if (sub == 0) {
        float sp = (acc > 20.f) ? acc : log1pf(expf(acc));
        g_gate[(size_t)t * NH + h] = sp;
    }
}

// =====================================================================
// Sliding-window attention. grid (T/32, 32), block 256. Unchanged.
// =====================================================================
#define ATTN_SMEM_FLOATS (TQ*132 + 128*VP + TQ*SPAD)
#define ATTN_SMEM_BYTES  (ATTN_SMEM_FLOATS * 4)

__global__ __launch_bounds__(256) void attn_k()
{
    extern __shared__ float sm[];
    float* qs  = sm;
    float* kvt = sm + TQ * 132;
    float* sc  = kvt + 128 * VP;

    const int t0  = blockIdx.x * TQ;
    const int h   = blockIdx.y;
    const int kvh = h >> 2;
    const int tid = threadIdx.x;
    const int wg  = tid >> 5;
    const int ln  = tid & 31;

    const int s_min  = max(0, t0 - (WINDOW - 1));
    const int s_end  = t0 + TQ;
    const int srange = s_end - s_min;
    const float scale = 0.08838834764831845f;

    for (int i = tid; i < TQ * 32; i += 256) {
        int m = i >> 5, c = (i & 31) * 4;
        float4 v = *(const float4*)(g_qkv + (size_t)(t0 + m) * QKVN + h * HD + c);
        v.x *= scale; v.y *= scale; v.z *= scale; v.w *= scale;
        *(float4*)(qs + m * 132 + c) = v;
    }

    for (int cs = s_min; cs < s_end; cs += 128) {
        const int cn = min(128, s_end - cs);
        __syncthreads();
        for (int i = tid; i < cn * 32; i += 256) {
            int j = i >> 5, c = (i & 31) * 4;
            float4 v = *(const float4*)(g_qkv + (size_t)(cs + j) * QKVN +
                                        QSIZE + kvh * HD + c);
            kvt[(c + 0) * KP + j] = v.x;
            kvt[(c + 1) * KP + j] = v.y;
            kvt[(c + 2) * KP + j] = v.z;
            kvt[(c + 3) * KP + j] = v.w;
        }
        __syncthreads();

        float acc[4][4];
#pragma unroll
        for (int i = 0; i < 4; i++)
#pragma unroll
            for (int j = 0; j < 4; j++) acc[i][j] = 0.f;

#pragma unroll 4
        for (int k = 0; k < HD; k++) {
            float a[4], b[4];
#pragma unroll
            for (int i = 0; i < 4; i++) a[i] = qs[(wg + 8 * i) * 132 + k];
#pragma unroll
            for (int j = 0; j < 4; j++) b[j] = kvt[k * KP + ln + 32 * j];
#pragma unroll
            for (int i = 0; i < 4; i++)
#pragma unroll
                for (int j = 0; j < 4; j++)
                    acc[i][j] = fmaf(a[i], b[j], acc[i][j]);
        }

        const int off = cs - s_min;
#pragma unroll
        for (int j = 0; j < 4; j++) {
            int n = ln + 32 * j;
            if (n < cn) {
                int s_abs = cs + n;
#pragma unroll
                for (int i = 0; i < 4; i++) {
                    int diff = (t0 + wg + 8 * i) - s_abs;
                    float val = (diff >= 0 && diff < WINDOW) ? acc[i][j] : -1e30f;
                    sc[(wg + 8 * i) * SPAD + off + n] = val;
                }
            }
        }
    }
    __syncthreads();

    for (int r = wg; r < TQ; r += 8) {
        float* row = sc + r * SPAD;
        float mx = -1e30f;
        for (int i = ln; i < srange; i += 32) mx = fmaxf(mx, row[i]);
#pragma unroll
        for (int o = 16; o; o >>= 1) mx = fmaxf(mx, __shfl_xor_sync(0xffffffffu, mx, o));
        float sum = 0.f;
        for (int i = ln; i < srange; i += 32) {
            float e = expf(row[i] - mx);
            row[i] = e;
            sum += e;
        }
#pragma unroll
        for (int o = 16; o; o >>= 1) sum += __shfl_xor_sync(0xffffffffu, sum, o);
        float inv = 1.f / sum;
        for (int i = ln; i < srange; i += 32) row[i] *= inv;
    }
    __syncthreads();

    float4 o[4];
#pragma unroll
    for (int i = 0; i < 4; i++) o[i] = make_float4(0.f, 0.f, 0.f, 0.f);

    for (int cs = s_min; cs < s_end; cs += 128) {
        const int cn = min(128, s_end - cs);
        __syncthreads();
        for (int i = tid; i < cn * 32; i += 256) {
            int j = i >> 5, c = (i & 31) * 4;
            float4 v = *(const float4*)(g_qkv + (size_t)(cs + j) * QKVN +
                                        QSIZE + KVSIZE + kvh * HD + c);
            *(float4*)(kvt + j * VP + c) = v;
        }
        __syncthreads();
        const int off = cs - s_min;
        for (int j = 0; j < cn; j++) {
            float4 v = *(float4*)(kvt + j * VP + ln * 4);
#pragma unroll
            for (int i = 0; i < 4; i++) {
                float p = sc[(wg + 8 * i) * SPAD + off + j];
                o[i].x = fmaf(p, v.x, o[i].x);
                o[i].y = fmaf(p, v.y, o[i].y);
                o[i].z = fmaf(p, v.z, o[i].z);
                o[i].w = fmaf(p, v.w, o[i].w);
            }
        }
    }

#pragma unroll
    for (int i = 0; i < 4; i++) {
        int m = wg + 8 * i;
        float g = g_gate[(size_t)(t0 + m) * NH + h];
        float4 r = o[i];
        r.x *= g; r.y *= g; r.z *= g; r.w *= g;
        *(float4*)(g_attn + (size_t)(t0 + m) * QSIZE + h * HD + ln * 4) = r;
    }
}

// =====================================================================
// launch
// =====================================================================
extern "C" void kernel_launch(void* const* d_in, const int* in_sizes, int n_in,
                              void* d_out, int out_size)
{
    const int*   positions = 0;
    const float* X    = 0;
    const float* Wqkv = 0;
    const float* Wo   = 0;
    const float* Wg   = 0;
    const float* qw   = 0;
    const float* kw   = 0;

    for (int i = 0; i < n_in; i++) {
        switch (in_sizes[i]) {
            case T_TOK:          positions = (const int*)d_in[i];     break;
            case T_TOK*HIDDEN:   X    = (const float*)d_in[i];        break;
            case HIDDEN*QKVN:    Wqkv = (const float*)d_in[i];        break;
            case QSIZE*HIDDEN:   Wo   = (const float*)d_in[i];        break;
            case HIDDEN*NH:      Wg   = (const float*)d_in[i];        break;
            case HD:             if (!qw) qw = (const float*)d_in[i];
                                 else     kw = (const float*)d_in[i]; break;
            default: break;
        }
    }

    float *qkv_p, *attn_p;
    cudaGetSymbolAddress((void**)&qkv_p,  g_qkv);
    cudaGetSymbolAddress((void**)&attn_p, g_attn);
    float* out = (float*)d_out;

    // 1) QKV GEMM (TF32 tensor cores): [2048,2048] x [2048,6144]
    gemm_tf32<<<dim3(QKVN / 128, T_TOK / 128), 256>>>(X, Wqkv, qkv_p,
                                                      T_TOK, QKVN, HIDDEN);
    // 2) RMSNorm + RoPE in place
    norm_rope_k<<<dim3(T_TOK, NH + NKV), 128>>>(positions, qw, kw);
    // 3) Gate
    gate_k<<<T_TOK, 256>>>(X, Wg);
    // 4) Attention (+ gate fused)
    cudaFuncSetAttribute(attn_k, cudaFuncAttributeMaxDynamicSharedMemorySize,
                         ATTN_SMEM_BYTES);
    attn_k<<<dim3(T_TOK / TQ, NH), 256, ATTN_SMEM_BYTES>>>();
    // 5) Output GEMM (TF32 tensor cores): [2048,4096] x [4096,2048]
    gemm_tf32<<<dim3(HIDDEN / 128, T_TOK / 128), 256>>>(attn_p, Wo, out,
                                                        T_TOK, HIDDEN, QSIZE);
    (void)out_size;
}

// round 12
// speedup vs baseline: 1.9525x; 1.1059x over previous
#include <cuda_runtime.h>
#include <math.h>
#include <stdint.h>

#define T_TOK 2048
#define HIDDEN 2048
#define NH 32
#define NKV 8
#define HD 128
#define QSIZE (NH*HD)              // 4096
#define KVSIZE (NKV*HD)            // 1024
#define QKVN (QSIZE + 2*KVSIZE)    // 6144
#define WINDOW 512
#define TQ 32
#define KP 129                     // K^T pitch (keys + 1)
#define VP 132                     // V row pitch
#define SCP 132                    // chunk-score row pitch

// -------- scratch (device globals: allocation-free) --------
__device__ float g_qkv[T_TOK * QKVN];     // 50.3 MB
__device__ float g_gate[T_TOK * NH];      // 0.26 MB
__device__ float g_attn[T_TOK * QSIZE];   // 33.5 MB

// =====================================================================
// TF32 tensor-core GEMM: C[M,N] = A[M,K] @ B[K,N], row-major.
// 128x128 block tile, 8 warps (2x4), warp tile 64x32, k-chunk 16.
// =====================================================================
__device__ __forceinline__ float to_tf32(float x)
{
    uint32_t r;
    asm("cvt.rna.tf32.f32 %0, %1;" : "=r"(r) : "f"(x));
    return __uint_as_float(r);
}

__device__ __forceinline__ void mma_tf32(
    float* d, const uint32_t* a, const uint32_t* b)
{
    asm volatile(
        "mma.sync.aligned.m16n8k8.row.col.f32.tf32.tf32.f32 "
        "{%0,%1,%2,%3}, {%4,%5,%6,%7}, {%8,%9}, {%0,%1,%2,%3};\n"
        : "+f"(d[0]), "+f"(d[1]), "+f"(d[2]), "+f"(d[3])
        : "r"(a[0]), "r"(a[1]), "r"(a[2]), "r"(a[3]),
          "r"(b[0]), "r"(b[1]));
}

__global__ __launch_bounds__(256) void gemm_tf32(
    const float* __restrict__ A, const float* __restrict__ B,
    float* __restrict__ C, int M, int N, int K)
{
    __shared__ float As[16][136];
    __shared__ float Bs[16][136];

    const int m0 = blockIdx.y * 128;
    const int n0 = blockIdx.x * 128;
    const int tid  = threadIdx.x;
    const int wid  = tid >> 5;
    const int lane = tid & 31;
    const int wm = (wid >> 2) * 64;
    const int wn = (wid & 3) * 32;
    const int grp = lane >> 2;
    const int tig = lane & 3;

    float acc[4][4][4];
#pragma unroll
    for (int mf = 0; mf < 4; mf++)
#pragma unroll
        for (int nf = 0; nf < 4; nf++)
#pragma unroll
            for (int r = 0; r < 4; r++) acc[mf][nf][r] = 0.f;

    const int am = tid >> 1;
    const int ak = (tid & 1) * 8;
    const int bk = tid >> 4;
    const int bn = (tid & 15) * 8;

    const float* Ap = A + (size_t)(m0 + am) * K + ak;
    const float* Bp = B + (size_t)bk * N + n0 + bn;

    for (int k0 = 0; k0 < K; k0 += 16) {
        float4 av0 = *(const float4*)(Ap + k0);
        float4 av1 = *(const float4*)(Ap + k0 + 4);
        float4 bv0 = *(const float4*)(Bp + (size_t)k0 * N);
        float4 bv1 = *(const float4*)(Bp + (size_t)k0 * N + 4);
        __syncthreads();
        As[ak + 0][am] = to_tf32(av0.x);
        As[ak + 1][am] = to_tf32(av0.y);
        As[ak + 2][am] = to_tf32(av0.z);
        As[ak + 3][am] = to_tf32(av0.w);
        As[ak + 4][am] = to_tf32(av1.x);
        As[ak + 5][am] = to_tf32(av1.y);
        As[ak + 6][am] = to_tf32(av1.z);
        As[ak + 7][am] = to_tf32(av1.w);
        Bs[bk][bn + 0] = to_tf32(bv0.x);
        Bs[bk][bn + 1] = to_tf32(bv0.y);
        Bs[bk][bn + 2] = to_tf32(bv0.z);
        Bs[bk][bn + 3] = to_tf32(bv0.w);
        Bs[bk][bn + 4] = to_tf32(bv1.x);
        Bs[bk][bn + 5] = to_tf32(bv1.y);
        Bs[bk][bn + 6] = to_tf32(bv1.z);
        Bs[bk][bn + 7] = to_tf32(bv1.w);
        __syncthreads();

#pragma unroll
        for (int ks = 0; ks < 16; ks += 8) {
            uint32_t af[4][4], bf[4][2];
#pragma unroll
            for (int mf = 0; mf < 4; mf++) {
                int row = wm + mf * 16 + grp;
                af[mf][0] = __float_as_uint(As[ks + tig    ][row]);
                af[mf][1] = __float_as_uint(As[ks + tig    ][row + 8]);
                af[mf][2] = __float_as_uint(As[ks + tig + 4][row]);
                af[mf][3] = __float_as_uint(As[ks + tig + 4][row + 8]);
            }
#pragma unroll
            for (int nf = 0; nf < 4; nf++) {
                int col = wn + nf * 8 + grp;
                bf[nf][0] = __float_as_uint(Bs[ks + tig    ][col]);
                bf[nf][1] = __float_as_uint(Bs[ks + tig + 4][col]);
            }
#pragma unroll
            for (int mf = 0; mf < 4; mf++)
#pragma unroll
                for (int nf = 0; nf < 4; nf++)
                    mma_tf32(acc[mf][nf], af[mf], bf[nf]);
        }
    }

#pragma unroll
    for (int mf = 0; mf < 4; mf++) {
        int row = m0 + wm + mf * 16 + grp;
#pragma unroll
        for (int nf = 0; nf < 4; nf++) {
            int col = n0 + wn + nf * 8 + 2 * tig;
            *(float2*)(C + (size_t)row * N + col) =
                make_float2(acc[mf][nf][0], acc[mf][nf][1]);
            *(float2*)(C + (size_t)(row + 8) * N + col) =
                make_float2(acc[mf][nf][2], acc[mf][nf][3]);
        }
    }
}

// =====================================================================
// RMSNorm + RoPE in place. grid (T, 40). sincosf(x, &s, &c): sin FIRST.
// =====================================================================
__global__ __launch_bounds__(128) void norm_rope_k(
    const int* __restrict__ pos,
    const float* __restrict__ qw, const float* __restrict__ kw)
{
    const int t  = blockIdx.x;
    const int hh = blockIdx.y;
    const bool is_q = (hh < NH);
    float* x = g_qkv + (size_t)t * QKVN +
               (is_q ? hh * HD : QSIZE + (hh - NH) * HD);
    const float* w = is_q ? qw : kw;
    const int d = threadIdx.x;

    float v = x[d];
    float ss = v * v;
#pragma unroll
    for (int o = 16; o; o >>= 1) ss += __shfl_xor_sync(0xffffffffu, ss, o);
    __shared__ float red[4];
    if ((d & 31) == 0) red[d >> 5] = ss;
    __syncthreads();
    float r = rsqrtf((red[0] + red[1] + red[2] + red[3]) * (1.0f / HD) + 1e-6f);

    __shared__ float xs[HD];
    xs[d] = v * r * w[d];
    __syncthreads();

    if (d < 64) {
        float inv = powf(10000.0f, -(float)(2 * d) * (1.0f / HD));
        float ang = (float)pos[t] * inv;
        float s, c;
        sincosf(ang, &s, &c);
        float x1 = xs[d], x2 = xs[d + 64];
        x[d]      = x1 * c - x2 * s;
        x[d + 64] = x2 * c + x1 * s;
    }
}

// =====================================================================
// Gate: softplus(X @ Wg). grid T, block 256.
// =====================================================================
__global__ __launch_bounds__(256) void gate_k(
    const float* __restrict__ X, const float* __restrict__ wg)
{
    const int t   = blockIdx.x;
    const int h   = threadIdx.x >> 3;
    const int sub = threadIdx.x & 7;
    const float* xr = X + (size_t)t * HIDDEN;

    float acc = 0.f;
    for (int k = sub; k < HIDDEN; k += 8)
        acc = fmaf(xr[k], wg[(size_t)k * NH + h], acc);
    acc += __shfl_xor_sync(0xffffffffu, acc, 1);
    acc += __shfl_xor_sync(0xffffffffu, acc, 2);
    acc += __shfl_xor_sync(0xffffffffu, acc, 4);
    if (sub == 0) {
        float sp = (acc > 20.f) ? acc : log1pf(expf(acc));
        g_gate[(size_t)t * NH + h] = sp;
    }
}

// =====================================================================
// Sliding-window attention, ONLINE SOFTMAX over 128-key chunks.
// grid (T/32, 32 heads), block 256. smem ~99.4 KB -> 2 CTAs/SM.
// =====================================================================
#define ATTN_SMEM_FLOATS (TQ*132 + 128*VP + TQ*SCP + 3*TQ)
#define ATTN_SMEM_BYTES  (ATTN_SMEM_FLOATS * 4)

__global__ __launch_bounds__(256) void attn_k()
{
    extern __shared__ float sm[];
    float* qs   = sm;                    // [TQ][132]
    float* kvt  = sm + TQ * 132;         // K^T [128][KP] or V [128][VP]
    float* sc   = kvt + 128 * VP;        // chunk scores [TQ][SCP]
    float* mrow = sc + TQ * SCP;         // running max [TQ]
    float* lrow = mrow + TQ;             // running sum [TQ]
    float* frow = lrow + TQ;             // per-chunk rescale [TQ]

    const int t0  = blockIdx.x * TQ;
    const int h   = blockIdx.y;
    const int kvh = h >> 2;
    const int tid = threadIdx.x;
    const int wg  = tid >> 5;
    const int ln  = tid & 31;

    const int s_min = max(0, t0 - (WINDOW - 1));
    const int s_end = t0 + TQ;
    const float scale = 0.08838834764831845f;  // 128^-0.5

    // ---- init row stats + load Q tile (pre-scaled) ----
    if (tid < TQ) { mrow[tid] = -1e30f; lrow[tid] = 0.f; }
    for (int i = tid; i < TQ * 32; i += 256) {
        int m = i >> 5, c = (i & 31) * 4;
        float4 v = *(const float4*)(g_qkv + (size_t)(t0 + m) * QKVN + h * HD + c);
        v.x *= scale; v.y *= scale; v.z *= scale; v.w *= scale;
        *(float4*)(qs + m * 132 + c) = v;
    }

    float4 o[4];
#pragma unroll
    for (int i = 0; i < 4; i++) o[i] = make_float4(0.f, 0.f, 0.f, 0.f);

    for (int cs = s_min; cs < s_end; cs += 128) {
        const int cn = min(128, s_end - cs);
        __syncthreads();      // prev chunk's PV done (kvt/sc reusable); Q ready

        // ---- load K chunk transposed ----
        for (int i = tid; i < cn * 32; i += 256) {
            int j = i >> 5, c = (i & 31) * 4;
            float4 v = *(const float4*)(g_qkv + (size_t)(cs + j) * QKVN +
                                        QSIZE + kvh * HD + c);
            kvt[(c + 0) * KP + j] = v.x;
            kvt[(c + 1) * KP + j] = v.y;
            kvt[(c + 2) * KP + j] = v.z;
            kvt[(c + 3) * KP + j] = v.w;
        }
        __syncthreads();

        // ---- QK^T (scalar FFMA, 4x4 microtile per thread) ----
        float acc[4][4];
#pragma unroll
        for (int i = 0; i < 4; i++)
#pragma unroll
            for (int j = 0; j < 4; j++) acc[i][j] = 0.f;

#pragma unroll 4
        for (int k = 0; k < HD; k++) {
            float a[4], b[4];
#pragma unroll
            for (int i = 0; i < 4; i++) a[i] = qs[(wg + 8 * i) * 132 + k];
#pragma unroll
            for (int j = 0; j < 4; j++) b[j] = kvt[k * KP + ln + 32 * j];
#pragma unroll
            for (int i = 0; i < 4; i++)
#pragma unroll
                for (int j = 0; j < 4; j++)
                    acc[i][j] = fmaf(a[i], b[j], acc[i][j]);
        }

#pragma unroll
        for (int j = 0; j < 4; j++) {
            int n = ln + 32 * j;
            if (n < cn) {
                int s_abs = cs + n;
#pragma unroll
                for (int i = 0; i < 4; i++) {
                    int diff = (t0 + wg + 8 * i) - s_abs;
                    float val = (diff >= 0 && diff < WINDOW) ? acc[i][j] : -1e30f;
                    sc[(wg + 8 * i) * SCP + n] = val;
                }
            }
        }
        __syncthreads();

        // ---- online softmax update (warp per row, rows strided by 8) ----
        for (int r = wg; r < TQ; r += 8) {
            float* row = sc + r * SCP;
            float mx = -1e30f;
            for (int j = ln; j < cn; j += 32) mx = fmaxf(mx, row[j]);
#pragma unroll
            for (int off = 16; off; off >>= 1)
                mx = fmaxf(mx, __shfl_xor_sync(0xffffffffu, mx, off));
            float mold = mrow[r];
            float mnew = fmaxf(mold, mx);
            float f    = expf(mold - mnew);   // 0 on first chunk
            float sum  = 0.f;
            for (int j = ln; j < cn; j += 32) {
                float e = expf(row[j] - mnew);
                row[j] = e;
                sum += e;
            }
#pragma unroll
            for (int off = 16; off; off >>= 1)
                sum += __shfl_xor_sync(0xffffffffu, sum, off);
            if (ln == 0) {
                mrow[r] = mnew;
                lrow[r] = lrow[r] * f + sum;
                frow[r] = f;
            }
        }
        __syncthreads();

        // ---- load V chunk (overwrites K buffer) ----
        for (int i = tid; i < cn * 32; i += 256) {
            int j = i >> 5, c = (i & 31) * 4;
            float4 v = *(const float4*)(g_qkv + (size_t)(cs + j) * QKVN +
                                        QSIZE + KVSIZE + kvh * HD + c);
            *(float4*)(kvt + j * VP + c) = v;
        }
        __syncthreads();

        // ---- PV accumulate with rescale ----
#pragma unroll
        for (int i = 0; i < 4; i++) {
            float f = frow[wg + 8 * i];
            o[i].x *= f; o[i].y *= f; o[i].z *= f; o[i].w *= f;
        }
        for (int j = 0; j < cn; j++) {
            float4 v = *(float4*)(kvt + j * VP + ln * 4);
#pragma unroll
            for (int i = 0; i < 4; i++) {
                float p = sc[(wg + 8 * i) * SCP + j];
                o[i].x = fmaf(p, v.x, o[i].x);
                o[i].y = fmaf(p, v.y, o[i].y);
                o[i].z = fmaf(p, v.z, o[i].z);
                o[i].w = fmaf(p, v.w, o[i].w);
            }
        }
    }

    // ---- epilogue: normalize, gate, store ----
#pragma unroll
    for (int i = 0; i < 4; i++) {
        int m = wg + 8 * i;
        float g = g_gate[(size_t)(t0 + m) * NH + h] / lrow[m];
        float4 r = o[i];
        r.x *= g; r.y *= g; r.z *= g; r.w *= g;
        *(float4*)(g_attn + (size_t)(t0 + m) * QSIZE + h * HD + ln * 4) = r;
    }
}

// =====================================================================
// launch
// =====================================================================
extern "C" void kernel_launch(void* const* d_in, const int* in_sizes, int n_in,
                              void* d_out, int out_size)
{
    const int*   positions = 0;
    const float* X    = 0;
    const float* Wqkv = 0;
    const float* Wo   = 0;
    const float* Wg   = 0;
    const float* qw   = 0;
    const float* kw   = 0;

    for (int i = 0; i < n_in; i++) {
        switch (in_sizes[i]) {
            case T_TOK:          positions = (const int*)d_in[i];     break;
            case T_TOK*HIDDEN:   X    = (const float*)d_in[i];        break;
            case HIDDEN*QKVN:    Wqkv = (const float*)d_in[i];        break;
            case QSIZE*HIDDEN:   Wo   = (const float*)d_in[i];        break;
            case HIDDEN*NH:      Wg   = (const float*)d_in[i];        break;
            case HD:             if (!qw) qw = (const float*)d_in[i];
                                 else     kw = (const float*)d_in[i]; break;
            default: break;
        }
    }

    float *qkv_p, *attn_p;
    cudaGetSymbolAddress((void**)&qkv_p,  g_qkv);
    cudaGetSymbolAddress((void**)&attn_p, g_attn);
    float* out = (float*)d_out;

    // 1) QKV GEMM (TF32): [2048,2048] x [2048,6144]
    gemm_tf32<<<dim3(QKVN / 128, T_TOK / 128), 256>>>(X, Wqkv, qkv_p,
                                                      T_TOK, QKVN, HIDDEN);
    // 2) RMSNorm + RoPE in place
    norm_rope_k<<<dim3(T_TOK, NH + NKV), 128>>>(positions, qw, kw);
    // 3) Gate
    gate_k<<<T_TOK, 256>>>(X, Wg);
    // 4) Attention (online softmax, 2 CTAs/SM)
    cudaFuncSetAttribute(attn_k, cudaFuncAttributeMaxDynamicSharedMemorySize,
                         ATTN_SMEM_BYTES);
    attn_k<<<dim3(T_TOK / TQ, NH), 256, ATTN_SMEM_BYTES>>>();
    // 5) Output GEMM (TF32): [2048,4096] x [4096,2048]
    gemm_tf32<<<dim3(HIDDEN / 128, T_TOK / 128), 256>>>(attn_p, Wo, out,
                                                        T_TOK, HIDDEN, QSIZE);
    (void)out_size;
}

// round 13
// speedup vs baseline: 2.4341x; 1.2466x over previous
#include <cuda_runtime.h>
#include <math.h>
#include <stdint.h>

#define T_TOK 2048
#define HIDDEN 2048
#define NH 32
#define NKV 8
#define HD 128
#define QSIZE (NH*HD)              // 4096
#define KVSIZE (NKV*HD)            // 1024
#define QKVN (QSIZE + 2*KVSIZE)    // 6144
#define WINDOW 512
#define TQ 32
#define AP 136                     // attention smem pitch (floats)

// -------- scratch (device globals: allocation-free) --------
__device__ float g_qkv[T_TOK * QKVN];     // 50.3 MB
__device__ float g_gate[T_TOK * NH];      // 0.26 MB
__device__ float g_attn[T_TOK * QSIZE];   // 33.5 MB

__device__ __forceinline__ float to_tf32(float x)
{
    uint32_t r;
    asm("cvt.rna.tf32.f32 %0, %1;" : "=r"(r) : "f"(x));
    return __uint_as_float(r);
}

__device__ __forceinline__ void mma_tf32(
    float* d, const uint32_t* a, const uint32_t* b)
{
    asm volatile(
        "mma.sync.aligned.m16n8k8.row.col.f32.tf32.tf32.f32 "
        "{%0,%1,%2,%3}, {%4,%5,%6,%7}, {%8,%9}, {%0,%1,%2,%3};\n"
        : "+f"(d[0]), "+f"(d[1]), "+f"(d[2]), "+f"(d[3])
        : "r"(a[0]), "r"(a[1]), "r"(a[2]), "r"(a[3]),
          "r"(b[0]), "r"(b[1]));
}

// =====================================================================
// TF32 tensor-core GEMM (unchanged from round 11/12).
// =====================================================================
__global__ __launch_bounds__(256) void gemm_tf32(
    const float* __restrict__ A, const float* __restrict__ B,
    float* __restrict__ C, int M, int N, int K)
{
    __shared__ float As[16][136];
    __shared__ float Bs[16][136];

    const int m0 = blockIdx.y * 128;
    const int n0 = blockIdx.x * 128;
    const int tid  = threadIdx.x;
    const int wid  = tid >> 5;
    const int lane = tid & 31;
    const int wm = (wid >> 2) * 64;
    const int wn = (wid & 3) * 32;
    const int grp = lane >> 2;
    const int tig = lane & 3;

    float acc[4][4][4];
#pragma unroll
    for (int mf = 0; mf < 4; mf++)
#pragma unroll
        for (int nf = 0; nf < 4; nf++)
#pragma unroll
            for (int r = 0; r < 4; r++) acc[mf][nf][r] = 0.f;

    const int am = tid >> 1;
    const int ak = (tid & 1) * 8;
    const int bk = tid >> 4;
    const int bn = (tid & 15) * 8;

    const float* Ap = A + (size_t)(m0 + am) * K + ak;
    const float* Bp = B + (size_t)bk * N + n0 + bn;

    for (int k0 = 0; k0 < K; k0 += 16) {
        float4 av0 = *(const float4*)(Ap + k0);
        float4 av1 = *(const float4*)(Ap + k0 + 4);
        float4 bv0 = *(const float4*)(Bp + (size_t)k0 * N);
        float4 bv1 = *(const float4*)(Bp + (size_t)k0 * N + 4);
        __syncthreads();
        As[ak + 0][am] = to_tf32(av0.x);
        As[ak + 1][am] = to_tf32(av0.y);
        As[ak + 2][am] = to_tf32(av0.z);
        As[ak + 3][am] = to_tf32(av0.w);
        As[ak + 4][am] = to_tf32(av1.x);
        As[ak + 5][am] = to_tf32(av1.y);
        As[ak + 6][am] = to_tf32(av1.z);
        As[ak + 7][am] = to_tf32(av1.w);
        Bs[bk][bn + 0] = to_tf32(bv0.x);
        Bs[bk][bn + 1] = to_tf32(bv0.y);
        Bs[bk][bn + 2] = to_tf32(bv0.z);
        Bs[bk][bn + 3] = to_tf32(bv0.w);
        Bs[bk][bn + 4] = to_tf32(bv1.x);
        Bs[bk][bn + 5] = to_tf32(bv1.y);
        Bs[bk][bn + 6] = to_tf32(bv1.z);
        Bs[bk][bn + 7] = to_tf32(bv1.w);
        __syncthreads();

#pragma unroll
        for (int ks = 0; ks < 16; ks += 8) {
            uint32_t af[4][4], bf[4][2];
#pragma unroll
            for (int mf = 0; mf < 4; mf++) {
                int row = wm + mf * 16 + grp;
                af[mf][0] = __float_as_uint(As[ks + tig    ][row]);
                af[mf][1] = __float_as_uint(As[ks + tig    ][row + 8]);
                af[mf][2] = __float_as_uint(As[ks + tig + 4][row]);
                af[mf][3] = __float_as_uint(As[ks + tig + 4][row + 8]);
            }
#pragma unroll
            for (int nf = 0; nf < 4; nf++) {
                int col = wn + nf * 8 + grp;
                bf[nf][0] = __float_as_uint(Bs[ks + tig    ][col]);
                bf[nf][1] = __float_as_uint(Bs[ks + tig + 4][col]);
            }
#pragma unroll
            for (int mf = 0; mf < 4; mf++)
#pragma unroll
                for (int nf = 0; nf < 4; nf++)
                    mma_tf32(acc[mf][nf], af[mf], bf[nf]);
        }
    }

#pragma unroll
    for (int mf = 0; mf < 4; mf++) {
        int row = m0 + wm + mf * 16 + grp;
#pragma unroll
        for (int nf = 0; nf < 4; nf++) {
            int col = n0 + wn + nf * 8 + 2 * tig;
            *(float2*)(C + (size_t)row * N + col) =
                make_float2(acc[mf][nf][0], acc[mf][nf][1]);
            *(float2*)(C + (size_t)(row + 8) * N + col) =
                make_float2(acc[mf][nf][2], acc[mf][nf][3]);
        }
    }
}

// =====================================================================
// RMSNorm + RoPE in place. sincosf(x, &s, &c): sin FIRST.
// =====================================================================
__global__ __launch_bounds__(128) void norm_rope_k(
    const int* __restrict__ pos,
    const float* __restrict__ qw, const float* __restrict__ kw)
{
    const int t  = blockIdx.x;
    const int hh = blockIdx.y;
    const bool is_q = (hh < NH);
    float* x = g_qkv + (size_t)t * QKVN +
               (is_q ? hh * HD : QSIZE + (hh - NH) * HD);
    const float* w = is_q ? qw : kw;
    const int d = threadIdx.x;

    float v = x[d];
    float ss = v * v;
#pragma unroll
    for (int o = 16; o; o >>= 1) ss += __shfl_xor_sync(0xffffffffu, ss, o);
    __shared__ float red[4];
    if ((d & 31) == 0) red[d >> 5] = ss;
    __syncthreads();
    float r = rsqrtf((red[0] + red[1] + red[2] + red[3]) * (1.0f / HD) + 1e-6f);

    __shared__ float xs[HD];
    xs[d] = v * r * w[d];
    __syncthreads();

    if (d < 64) {
        float inv = powf(10000.0f, -(float)(2 * d) * (1.0f / HD));
        float ang = (float)pos[t] * inv;
        float s, c;
        sincosf(ang, &s, &c);
        float x1 = xs[d], x2 = xs[d + 64];
        x[d]      = x1 * c - x2 * s;
        x[d + 64] = x2 * c + x1 * s;
    }
}

// =====================================================================
// Gate: softplus(X @ Wg). grid T, block 256.
// =====================================================================
__global__ __launch_bounds__(256) void gate_k(
    const float* __restrict__ X, const float* __restrict__ wg)
{
    const int t   = blockIdx.x;
    const int h   = threadIdx.x >> 3;
    const int sub = threadIdx.x & 7;
    const float* xr = X + (size_t)t * HIDDEN;

    float acc = 0.f;
    for (int k = sub; k < HIDDEN; k += 8)
        acc = fmaf(xr[k], wg[(size_t)k * NH + h], acc);
    acc += __shfl_xor_sync(0xffffffffu, acc, 1);
    acc += __shfl_xor_sync(0xffffffffu, acc, 2);
    acc += __shfl_xor_sync(0xffffffffu, acc, 4);
    if (sub == 0) {
        float sp = (acc > 20.f) ? acc : log1pf(expf(acc));
        g_gate[(size_t)t * NH + h] = sp;
    }
}

// =====================================================================
// Sliding-window attention with TF32 MMA for QK^T and PV.
// grid (T/32, 32 heads), block 256 (8 warps), online softmax.
// Warp layout: wm = (wid>>2)*16 (M=32 => 2 warp rows),
//              wn = (wid&3)*32  (N=128 => 4 warp cols).
// K and V both loaded NATURAL [key][dim] (row.col mma: B[k][n] buffer).
// smem: Q[32][AP] + KV[128][AP] + SC[32][AP] + stats = 104.8 KB.
// =====================================================================
#define ATTN_SMEM_FLOATS ((TQ + 128 + TQ) * AP + 3 * TQ)
#define ATTN_SMEM_BYTES  (ATTN_SMEM_FLOATS * 4)

__global__ __launch_bounds__(256) void attn_k()
{
    extern __shared__ float sm[];
    float* qs   = sm;                    // Q  [TQ][AP] (tf32, pre-scaled)
    float* kv   = sm + TQ * AP;          // K or V [128][AP] natural
    float* sc   = kv + 128 * AP;         // scores / P [TQ][AP]
    float* mrow = sc + TQ * AP;          // running max [TQ]
    float* lrow = mrow + TQ;             // running sum [TQ]
    float* frow = lrow + TQ;             // rescale [TQ]

    const int t0  = blockIdx.x * TQ;
    const int h   = blockIdx.y;
    const int kvh = h >> 2;
    const int tid = threadIdx.x;
    const int wid = tid >> 5;
    const int ln  = tid & 31;
    const int wm  = (wid >> 2) * 16;     // 0,16
    const int wn  = (wid & 3) * 32;      // 0,32,64,96
    const int grp = ln >> 2;             // 0..7
    const int tig = ln & 3;              // 0..3

    const int s_min = max(0, t0 - (WINDOW - 1));
    const int s_end = t0 + TQ;
    const float scale = 0.08838834764831845f;  // 128^-0.5

    if (tid < TQ) { mrow[tid] = -1e30f; lrow[tid] = 0.f; }
    // Q tile: [TQ][HD], pre-scaled, tf32
    for (int i = tid; i < TQ * 32; i += 256) {
        int m = i >> 5, c = (i & 31) * 4;
        float4 v = *(const float4*)(g_qkv + (size_t)(t0 + m) * QKVN + h * HD + c);
        qs[m * AP + c + 0] = to_tf32(v.x * scale);
        qs[m * AP + c + 1] = to_tf32(v.y * scale);
        qs[m * AP + c + 2] = to_tf32(v.z * scale);
        qs[m * AP + c + 3] = to_tf32(v.w * scale);
    }

    // Output accumulators: 4 n-frags of m16n8 (rows wm+grp, wm+grp+8)
    float o[4][4];
#pragma unroll
    for (int nf = 0; nf < 4; nf++)
#pragma unroll
        for (int r = 0; r < 4; r++) o[nf][r] = 0.f;

    const int row0 = wm + grp;
    const int row1 = row0 + 8;

    for (int cs = s_min; cs < s_end; cs += 128) {
        const int cn = min(128, s_end - cs);
        __syncthreads();   // prev PV done; Q/stats ready

        // ---- load K chunk natural [key][dim], tf32 ----
        for (int i = tid; i < cn * 32; i += 256) {
            int j = i >> 5, c = (i & 31) * 4;
            float4 v = *(const float4*)(g_qkv + (size_t)(cs + j) * QKVN +
                                        QSIZE + kvh * HD + c);
            kv[j * AP + c + 0] = to_tf32(v.x);
            kv[j * AP + c + 1] = to_tf32(v.y);
            kv[j * AP + c + 2] = to_tf32(v.z);
            kv[j * AP + c + 3] = to_tf32(v.w);
        }
        __syncthreads();

        // ---- QK^T via mma: M=32, N=128 keys, K=128 dims ----
        float acc[4][4];
#pragma unroll
        for (int nf = 0; nf < 4; nf++)
#pragma unroll
            for (int r = 0; r < 4; r++) acc[nf][r] = 0.f;

#pragma unroll
        for (int ks = 0; ks < 16; ks++) {
            const int k0 = ks * 8;
            uint32_t a[4];
            a[0] = __float_as_uint(qs[row0 * AP + k0 + tig]);
            a[1] = __float_as_uint(qs[row1 * AP + k0 + tig]);
            a[2] = __float_as_uint(qs[row0 * AP + k0 + tig + 4]);
            a[3] = __float_as_uint(qs[row1 * AP + k0 + tig + 4]);
#pragma unroll
            for (int nf = 0; nf < 4; nf++) {
                const int key = wn + nf * 8 + grp;
                uint32_t b[2];
                b[0] = __float_as_uint(kv[key * AP + k0 + tig]);
                b[1] = __float_as_uint(kv[key * AP + k0 + tig + 4]);
                mma_tf32(acc[nf], a, b);
            }
        }

        // ---- masked score write (ALL 128 cols covered) ----
#pragma unroll
        for (int nf = 0; nf < 4; nf++) {
            const int col = wn + nf * 8 + 2 * tig;
            const int s0 = cs + col, s1 = s0 + 1;
            int d00 = (t0 + row0) - s0, d01 = (t0 + row0) - s1;
            int d10 = (t0 + row1) - s0, d11 = (t0 + row1) - s1;
            sc[row0 * AP + col]     = (d00 >= 0 && d00 < WINDOW) ? acc[nf][0] : -1e30f;
            sc[row0 * AP + col + 1] = (d01 >= 0 && d01 < WINDOW) ? acc[nf][1] : -1e30f;
            sc[row1 * AP + col]     = (d10 >= 0 && d10 < WINDOW) ? acc[nf][2] : -1e30f;
            sc[row1 * AP + col + 1] = (d11 >= 0 && d11 < WINDOW) ? acc[nf][3] : -1e30f;
        }
        __syncthreads();

        // ---- online softmax (warp per row, full 128 cols); P stored tf32 ----
        for (int r = wid; r < TQ; r += 8) {
            float* row = sc + r * AP;
            float mx = -1e30f;
#pragma unroll 4
            for (int j = ln; j < 128; j += 32) mx = fmaxf(mx, row[j]);
#pragma unroll
            for (int off = 16; off; off >>= 1)
                mx = fmaxf(mx, __shfl_xor_sync(0xffffffffu, mx, off));
            float mold = mrow[r];
            float mnew = fmaxf(mold, mx);
            float f    = expf(mold - mnew);
            float sum  = 0.f;
#pragma unroll 4
            for (int j = ln; j < 128; j += 32) {
                float e = expf(row[j] - mnew);
                row[j] = to_tf32(e);
                sum += e;
            }
#pragma unroll
            for (int off = 16; off; off >>= 1)
                sum += __shfl_xor_sync(0xffffffffu, sum, off);
            if (ln == 0) {
                mrow[r] = mnew;
                lrow[r] = lrow[r] * f + sum;
                frow[r] = f;
            }
        }
        __syncthreads();

        // ---- load V chunk natural [key][dim] (overwrites K) ----
        for (int i = tid; i < cn * 32; i += 256) {
            int j = i >> 5, c = (i & 31) * 4;
            float4 v = *(const float4*)(g_qkv + (size_t)(cs + j) * QKVN +
                                        QSIZE + KVSIZE + kvh * HD + c);
            kv[j * AP + c + 0] = to_tf32(v.x);
            kv[j * AP + c + 1] = to_tf32(v.y);
            kv[j * AP + c + 2] = to_tf32(v.z);
            kv[j * AP + c + 3] = to_tf32(v.w);
        }
        // zero tail keys (avoid 0 x NaN from uninitialized smem on partial chunks)
        for (int i = cn * 32 + tid; i < 128 * 32; i += 256) {
            int j = i >> 5, c = (i & 31) * 4;
            kv[j * AP + c + 0] = 0.f;
            kv[j * AP + c + 1] = 0.f;
            kv[j * AP + c + 2] = 0.f;
            kv[j * AP + c + 3] = 0.f;
        }
        __syncthreads();

        // ---- rescale o, then PV via mma: M=32, N=128 dims, K=128 keys ----
        {
            float f0 = frow[row0], f1 = frow[row1];
#pragma unroll
            for (int nf = 0; nf < 4; nf++) {
                o[nf][0] *= f0; o[nf][1] *= f0;
                o[nf][2] *= f1; o[nf][3] *= f1;
            }
        }
#pragma unroll
        for (int ks = 0; ks < 16; ks++) {
            const int k0 = ks * 8;
            uint32_t a[4];
            a[0] = __float_as_uint(sc[row0 * AP + k0 + tig]);
            a[1] = __float_as_uint(sc[row1 * AP + k0 + tig]);
            a[2] = __float_as_uint(sc[row0 * AP + k0 + tig + 4]);
            a[3] = __float_as_uint(sc[row1 * AP + k0 + tig + 4]);
#pragma unroll
            for (int nf = 0; nf < 4; nf++) {
                const int dimc = wn + nf * 8 + grp;
                uint32_t b[2];
                b[0] = __float_as_uint(kv[(k0 + tig)     * AP + dimc]);
                b[1] = __float_as_uint(kv[(k0 + tig + 4) * AP + dimc]);
                mma_tf32(o[nf], a, b);
            }
        }
    }
    __syncthreads();

    // ---- epilogue: normalize by l, gate, store ----
    {
        float g0 = g_gate[(size_t)(t0 + row0) * NH + h] / lrow[row0];
        float g1 = g_gate[(size_t)(t0 + row1) * NH + h] / lrow[row1];
#pragma unroll
        for (int nf = 0; nf < 4; nf++) {
            const int col = wn + nf * 8 + 2 * tig;
            *(float2*)(g_attn + (size_t)(t0 + row0) * QSIZE + h * HD + col) =
                make_float2(o[nf][0] * g0, o[nf][1] * g0);
            *(float2*)(g_attn + (size_t)(t0 + row1) * QSIZE + h * HD + col) =
                make_float2(o[nf][2] * g1, o[nf][3] * g1);
        }
    }
}

// =====================================================================
// launch
// =====================================================================
extern "C" void kernel_launch(void* const* d_in, const int* in_sizes, int n_in,
                              void* d_out, int out_size)
{
    const int*   positions = 0;
    const float* X    = 0;
    const float* Wqkv = 0;
    const float* Wo   = 0;
    const float* Wg   = 0;
    const float* qw   = 0;
    const float* kw   = 0;

    for (int i = 0; i < n_in; i++) {
        switch (in_sizes[i]) {
            case T_TOK:          positions = (const int*)d_in[i];     break;
            case T_TOK*HIDDEN:   X    = (const float*)d_in[i];        break;
            case HIDDEN*QKVN:    Wqkv = (const float*)d_in[i];        break;
            case QSIZE*HIDDEN:   Wo   = (const float*)d_in[i];        break;
            case HIDDEN*NH:      Wg   = (const float*)d_in[i];        break;
            case HD:             if (!qw) qw = (const float*)d_in[i];
                                 else     kw = (const float*)d_in[i]; break;
            default: break;
        }
    }

    float *qkv_p, *attn_p;
    cudaGetSymbolAddress((void**)&qkv_p,  g_qkv);
    cudaGetSymbolAddress((void**)&attn_p, g_attn);
    float* out = (float*)d_out;

    // 1) QKV GEMM (TF32): [2048,2048] x [2048,6144]
    gemm_tf32<<<dim3(QKVN / 128, T_TOK / 128), 256>>>(X, Wqkv, qkv_p,
                                                      T_TOK, QKVN, HIDDEN);
    // 2) RMSNorm + RoPE in place
    norm_rope_k<<<dim3(T_TOK, NH + NKV), 128>>>(positions, qw, kw);
    // 3) Gate
    gate_k<<<T_TOK, 256>>>(X, Wg);
    // 4) Attention (TF32 mma QK + PV, online softmax)
    cudaFuncSetAttribute(attn_k, cudaFuncAttributeMaxDynamicSharedMemorySize,
                         ATTN_SMEM_BYTES);
    attn_k<<<dim3(T_TOK / TQ, NH), 256, ATTN_SMEM_BYTES>>>();
    // 5) Output GEMM (TF32): [2048,4096] x [4096,2048]
    gemm_tf32<<<dim3(HIDDEN / 128, T_TOK / 128), 256>>>(attn_p, Wo, out,
                                                        T_TOK, HIDDEN, QSIZE);
    (void)out_size;
}